// round 7
// baseline (speedup 1.0000x reference)
#include <cuda_runtime.h>
#include <cuda_bf16.h>
#include <cstdint>
#include <stdint.h>
#include <math.h>

#define BB 128
#define TT 32
#define EE 512
#define HH 512
#define VV 10000
#define CF 2048
#define VPAD 10112            // 79 n-tiles of 128

#define APITCH 40             // bf16 elements per smem row (80B, conflict-free)
#define TILEB (128*APITCH*2)  // logits: 10240 bytes per tile
#define BUFB (4*TILEB)        // logits buffer

// recurrent tiles
#define NCTA_R 32
#define RTILEA (128*APITCH*2) // 10240 B per A plane (hi or lo)
#define RTILEW (32*APITCH*2)  // 2560 B per W plane
#define RBUF   (2*RTILEA + 2*RTILEW)   // 25600
#define RSMEM  (2*RBUF)                // 51200

typedef unsigned long long ull;

// ---------------- scratch (device globals; no allocations allowed) ----------
__device__ float g_h0[BB*HH];
__device__ float g_emb[TT*BB*EE];
__device__ float g_XU[TT*BB*HH];
__device__ float g_XR[TT*BB*HH];
__device__ float g_XC[TT*BB*HH];
__device__ float g_H0a[BB*HH];
__device__ float g_H0b[BB*HH];
__device__ float g_H1[TT*BB*HH];
__device__ float g_u[BB*HH];
__device__ unsigned g_bar;
__device__ unsigned g_gen;
// bf16 split buffers: row = [hi(512) | lo(512)]
__device__ __nv_bfloat16 g_A2[4096*1024];       // h1 splits per t (logits A + h1prev)
__device__ __nv_bfloat16 g_B2[VPAD*1024];
__device__ __nv_bfloat16 g_H0s[BB*1024];        // h0 split (current)
__device__ __nv_bfloat16 g_h0s[BB*1024];        // initial h0 split (stable)
__device__ __nv_bfloat16 g_rhs[BB*1024];        // r*h split
// weight splits: [n=512 rows][hi K | lo K]
__device__ __nv_bfloat16 g_W0s[3*512*1024];     // K=512 (h-part of layer0)
__device__ __nv_bfloat16 g_W1s[3*512*2048];     // K=1024 (layer1)

__device__ __forceinline__ float sigmoidf_(float v){ return 1.f/(1.f+__expf(-v)); }

// packed f32x2 helpers (FFMA2 path, prep GEMMs)
__device__ __forceinline__ void fma2(ull &acc, ull a, ull b){
    asm("fma.rn.f32x2 %0, %1, %2, %0;" : "+l"(acc) : "l"(a), "l"(b));
}
__device__ __forceinline__ ull dup2(float x){
    ull r; asm("mov.b64 %0, {%1, %1};" : "=l"(r) : "f"(x)); return r;
}
__device__ __forceinline__ float2 unp2(ull v){
    float2 f; asm("mov.b64 {%0, %1}, %2;" : "=f"(f.x), "=f"(f.y) : "l"(v)); return f;
}

// ---------------- mma.sync helpers ------------------------------------------
__device__ __forceinline__ uint32_t smem_u32(const void* p){
    uint32_t a;
    asm("{ .reg .u64 t; cvta.to.shared.u64 t, %1; cvt.u32.u64 %0, t; }" : "=r"(a) : "l"(p));
    return a;
}
__device__ __forceinline__ void cpa16(uint32_t dst, const void* src){
    asm volatile("cp.async.cg.shared.global [%0], [%1], 16;" :: "r"(dst), "l"(src));
}
__device__ __forceinline__ void cpa_commit(){
    asm volatile("cp.async.commit_group;" ::: "memory");
}
template<int N> __device__ __forceinline__ void cpa_wait(){
    asm volatile("cp.async.wait_group %0;" :: "n"(N) : "memory");
}
__device__ __forceinline__ void ldx4(uint32_t* r, uint32_t addr){
    asm volatile("ldmatrix.sync.aligned.m8n8.x4.shared.b16 {%0,%1,%2,%3}, [%4];"
        : "=r"(r[0]), "=r"(r[1]), "=r"(r[2]), "=r"(r[3]) : "r"(addr));
}
__device__ __forceinline__ void mma16816(float* d, const uint32_t* a,
                                         uint32_t b0, uint32_t b1){
    asm volatile("mma.sync.aligned.m16n8k16.row.col.f32.bf16.bf16.f32 "
        "{%0,%1,%2,%3}, {%4,%5,%6,%7}, {%8,%9}, {%0,%1,%2,%3};"
        : "+f"(d[0]), "+f"(d[1]), "+f"(d[2]), "+f"(d[3])
        : "r"(a[0]), "r"(a[1]), "r"(a[2]), "r"(a[3]), "r"(b0), "r"(b1));
}

// ---------------- embedding gather ------------------------------------------
__global__ void k_gather(const int* __restrict__ tok, const float* __restrict__ emb){
    int row = blockIdx.x;            // t*BB + b
    int t = row >> 7, b = row & 127;
    int v = tok[b*TT + t];
    const float4* src = (const float4*)(emb + (long)v*EE);
    float4* dst = (float4*)(g_emb + (long)row*EE);
    dst[threadIdx.x] = src[threadIdx.x];
}

// ---------------- big fp32 GEMM, 128x64 tile, FFMA2 (prep + h0) -------------
template<int EPI>
__global__ void __launch_bounds__(256)
k_gemmL(const float* __restrict__ A, const float* __restrict__ Bm,
        const float* __restrict__ bias, float* __restrict__ C,
        int M, int N, int K, int lda, int ldb, int ldc)
{
    __shared__ __align__(16) float As[16*132];
    __shared__ __align__(16) float Bs[16*68];
    int tid = threadIdx.x;
    int ty = tid >> 4, tx = tid & 15;
    int m0 = blockIdx.y * 128, n0 = blockIdx.x * 64;
    int ar = tid >> 1, ac = (tid & 1) * 8;
    int br = tid >> 4, bc = (tid & 15) * 4;
    bool bok = (n0 + bc) < N;

    ull acc[4][4] = {};
    float4 a0, a1, b0;

    a0 = *(const float4*)(A + (long)(m0+ar)*lda + ac);
    a1 = *(const float4*)(A + (long)(m0+ar)*lda + ac + 4);
    b0 = bok ? *(const float4*)(Bm + (long)br*ldb + n0 + bc)
             : make_float4(0.f,0.f,0.f,0.f);
    As[(ac+0)*132+ar]=a0.x; As[(ac+1)*132+ar]=a0.y; As[(ac+2)*132+ar]=a0.z; As[(ac+3)*132+ar]=a0.w;
    As[(ac+4)*132+ar]=a1.x; As[(ac+5)*132+ar]=a1.y; As[(ac+6)*132+ar]=a1.z; As[(ac+7)*132+ar]=a1.w;
    *(float4*)&Bs[br*68+bc] = b0;
    __syncthreads();

    int nch = K >> 4;
    for (int ch = 1; ch <= nch; ch++){
        if (ch < nch){
            int k0 = ch * 16;
            a0 = *(const float4*)(A + (long)(m0+ar)*lda + k0 + ac);
            a1 = *(const float4*)(A + (long)(m0+ar)*lda + k0 + ac + 4);
            b0 = bok ? *(const float4*)(Bm + (long)(k0+br)*ldb + n0 + bc)
                     : make_float4(0.f,0.f,0.f,0.f);
        }
#pragma unroll
        for (int kk = 0; kk < 16; kk++){
            ull av[4];
#pragma unroll
            for (int p = 0; p < 4; p++)
                av[p] = *(const ull*)(As + kk*132 + ty*8 + 2*p);
            float4 bv = *(const float4*)(Bs + kk*68 + tx*4);
            ull bb0 = dup2(bv.x), bb1 = dup2(bv.y), bb2 = dup2(bv.z), bb3 = dup2(bv.w);
#pragma unroll
            for (int p = 0; p < 4; p++){
                fma2(acc[p][0], av[p], bb0);
                fma2(acc[p][1], av[p], bb1);
                fma2(acc[p][2], av[p], bb2);
                fma2(acc[p][3], av[p], bb3);
            }
        }
        if (ch < nch){
            __syncthreads();
            As[(ac+0)*132+ar]=a0.x; As[(ac+1)*132+ar]=a0.y; As[(ac+2)*132+ar]=a0.z; As[(ac+3)*132+ar]=a0.w;
            As[(ac+4)*132+ar]=a1.x; As[(ac+5)*132+ar]=a1.y; As[(ac+6)*132+ar]=a1.z; As[(ac+7)*132+ar]=a1.w;
            *(float4*)&Bs[br*68+bc] = b0;
            __syncthreads();
        }
    }

#pragma unroll
    for (int p = 0; p < 4; p++){
#pragma unroll
        for (int j = 0; j < 4; j++){
            float2 v = unp2(acc[p][j]);
            int n = n0 + tx*4 + j;
            if (n < N){
                float bz = bias[n];
                float r0 = v.x + bz, r1 = v.y + bz;
                if (EPI == 1){ r0 = tanhf(r0); r1 = tanhf(r1); }
                int row0 = ty*8 + 2*p;
                C[(long)(m0+row0)*ldc + n] = r0;
                C[(long)(m0+row0+1)*ldc + n] = r1;
            }
        }
    }
}

// ---------------- packers ---------------------------------------------------
// out_W [512,10000] -> g_B2 [VPAD rows][hi512|lo512]
__global__ void k_packB(const float* __restrict__ W){
    __shared__ float tile[32][65];
    int n0 = blockIdx.x * 64, k0 = blockIdx.y * 32;
    int tid = threadIdx.x;
#pragma unroll
    for (int p = 0; p < 8; p++){
        int idx = tid + p*256;
        int kk = idx >> 6, nn = idx & 63;
        int n = n0 + nn;
        tile[kk][nn] = (n < VV) ? W[(long)(k0+kk)*VV + n] : 0.f;
    }
    __syncthreads();
#pragma unroll
    for (int p = 0; p < 8; p++){
        int idx = tid + p*256;
        int nn = idx >> 5, kk = idx & 31;
        float v = tile[kk][nn];
        __nv_bfloat16 hi = __float2bfloat16(v);
        __nv_bfloat16 lo = __float2bfloat16(v - __bfloat162float(hi));
        long base = (long)(n0+nn)*1024 + k0 + kk;
        g_B2[base]       = hi;
        g_B2[base + 512] = lo;
    }
}

// weight W [K,512] -> dst [512 rows][hi K | lo K]
__global__ void k_packW(const float* __restrict__ W, __nv_bfloat16* __restrict__ dst, int K){
    __shared__ float tile[32][65];
    int n0 = blockIdx.x * 64, k0 = blockIdx.y * 32;
    int tid = threadIdx.x;
#pragma unroll
    for (int p = 0; p < 8; p++){
        int idx = tid + p*256;
        int kk = idx >> 6, nn = idx & 63;
        tile[kk][nn] = W[(long)(k0+kk)*HH + n0 + nn];
    }
    __syncthreads();
#pragma unroll
    for (int p = 0; p < 8; p++){
        int idx = tid + p*256;
        int nn = idx >> 5, kk = idx & 31;
        float v = tile[kk][nn];
        __nv_bfloat16 hi = __float2bfloat16(v);
        __nv_bfloat16 lo = __float2bfloat16(v - __bfloat162float(hi));
        long base = (long)(n0+nn)*(2*K) + k0 + kk;
        dst[base]     = hi;
        dst[base + K] = lo;
    }
}

// split initial h0 into g_H0s (working) and g_h0s (stable, for h1prev at t=0)
__global__ void k_splitH0(){
    int i = blockIdx.x * blockDim.x + threadIdx.x;   // 0..65535
    int m = i >> 9, k = i & 511;
    float v = g_h0[i];
    __nv_bfloat16 hi = __float2bfloat16(v);
    __nv_bfloat16 lo = __float2bfloat16(v - __bfloat162float(hi));
    g_H0s[m*1024 + k]       = hi;
    g_H0s[m*1024 + 512 + k] = lo;
    g_h0s[m*1024 + k]       = hi;
    g_h0s[m*1024 + 512 + k] = lo;
}

// ---------------- mma.sync bf16 logits GEMM (unchanged from R6) -------------
__global__ void __launch_bounds__(256)
k_logits_mma(const float* __restrict__ bias, float* __restrict__ out)
{
    extern __shared__ __align__(16) char dsm[];
    int tid = threadIdx.x, lane = tid & 31, wid = tid >> 5;
    int t = blockIdx.y;
    int n0 = blockIdx.x * 128;
    int wm = (wid & 1) * 64, wn = (wid >> 1) * 32;

    const __nv_bfloat16* Abase = g_A2 + (long)t*128*1024;
    const __nv_bfloat16* Bbase = g_B2 + (long)n0*1024;
    uint32_t sbase = smem_u32(dsm);

    float acc[4][4][4];
#pragma unroll
    for (int i = 0; i < 4; i++)
#pragma unroll
        for (int j = 0; j < 4; j++)
#pragma unroll
            for (int q = 0; q < 4; q++) acc[i][j][q] = 0.f;

    int aoff = (wm + (lane & 15)) * APITCH + (lane >> 4) * 8;
    int boff = (wn + (lane & 7) + ((lane >> 4) << 3)) * APITCH + ((lane >> 3) & 1) * 8;

    auto load_chunk = [&](int c, int bi){
        int k0 = c * 32;
        uint32_t bu = sbase + bi * BUFB;
#pragma unroll
        for (int it = 0; it < 8; it++){
            int e = tid + it * 256;
            int tile = e >> 9;
            int r = (e >> 2) & 127;
            int seg = e & 3;
            const __nv_bfloat16* src =
                (tile < 2 ? Abase : Bbase) + (long)r*1024 + ((tile & 1) ? 512 : 0) + k0 + seg*8;
            cpa16(bu + tile*TILEB + (r*APITCH + seg*8)*2, src);
        }
        cpa_commit();
    };

    load_chunk(0, 0);
    for (int c = 0; c < 16; c++){
        if (c + 1 < 16){ load_chunk(c+1, (c+1) & 1); cpa_wait<1>(); }
        else           { cpa_wait<0>(); }
        __syncthreads();
        uint32_t bu = sbase + (c & 1) * BUFB;
        uint32_t uAh = bu, uAl = bu + TILEB, uBh = bu + 2*TILEB, uBl = bu + 3*TILEB;
#pragma unroll
        for (int ks = 0; ks < 2; ks++){
            uint32_t ah[4][4], al[4][4], bh[2][4], bl[2][4];
#pragma unroll
            for (int mi = 0; mi < 4; mi++){
                uint32_t ao = (uint32_t)(aoff + mi*16*APITCH + ks*16) * 2;
                ldx4(ah[mi], uAh + ao);
                ldx4(al[mi], uAl + ao);
            }
#pragma unroll
            for (int p = 0; p < 2; p++){
                uint32_t bo = (uint32_t)(boff + p*16*APITCH + ks*16) * 2;
                ldx4(bh[p], uBh + bo);
                ldx4(bl[p], uBl + bo);
            }
#pragma unroll
            for (int mi = 0; mi < 4; mi++)
#pragma unroll
                for (int nj = 0; nj < 4; nj++){
                    int p = nj >> 1, q = (nj & 1) * 2;
                    mma16816(acc[mi][nj], ah[mi], bh[p][q], bh[p][q+1]);
                    mma16816(acc[mi][nj], al[mi], bh[p][q], bh[p][q+1]);
                    mma16816(acc[mi][nj], ah[mi], bl[p][q], bl[p][q+1]);
                }
        }
        __syncthreads();
    }

    int lr = lane >> 2, lc = (lane & 3) * 2;
    long strideB = TT * (long)VV;
#pragma unroll
    for (int mi = 0; mi < 4; mi++){
        int b0 = wm + mi*16 + lr;
        long base0 = (long)b0*strideB + (long)t*VV;
#pragma unroll
        for (int nj = 0; nj < 4; nj++){
            int n = n0 + wn + nj*8 + lc;
            const float* a4 = acc[mi][nj];
            if (n < VV){
                float bz = bias[n];
                out[base0 + n]               = a4[0] + bz;
                out[base0 + 8*strideB + n]   = a4[2] + bz;
            }
            if (n + 1 < VV){
                float bz = bias[n+1];
                out[base0 + n + 1]             = a4[1] + bz;
                out[base0 + 8*strideB + n + 1] = a4[3] + bz;
            }
        }
    }
}

// ---------------- barrier state reset (per graph replay) --------------------
__global__ void k_reset(){ g_bar = 0u; g_gen = 0u; }

// ---------------- grid-wide sense barrier (NCTA_R CTAs) ---------------------
__device__ __forceinline__ void gsyncN(unsigned &my_gen){
    __syncthreads();
    if (threadIdx.x == 0){
        __threadfence();
        my_gen++;
        if (atomicAdd(&g_bar, 1u) == NCTA_R-1u){
            atomicExch(&g_bar, 0u);
            __threadfence();
            atomicExch(&g_gen, my_gen);
        } else {
            while (*(volatile unsigned*)&g_gen < my_gen) { }
            __threadfence();
        }
    }
    __syncthreads();
}

// ---------------- recurrent phase GEMM: C[128 x NT] = split-mma -------------
// A0/A1: [128][hi512|lo512]; chunk ci<16 -> A0, else A1. Wp: [NT rows][hi K|lo K]
template<int NT, int NCH>
__device__ __forceinline__ void mma_phaseR(
    uint32_t sbase, int tid, int wid, int lane,
    const __nv_bfloat16* __restrict__ A0,
    const __nv_bfloat16* __restrict__ A1,
    const __nv_bfloat16* __restrict__ Wp,
    int wstride, int wlo,
    float acc[NT/8][4])
{
#pragma unroll
    for (int i = 0; i < NT/8; i++)
#pragma unroll
        for (int q = 0; q < 4; q++) acc[i][q] = 0.f;

    auto ld = [&](int ci, int bi){
        uint32_t bu = sbase + bi*RBUF;
        const __nv_bfloat16* As = (ci < 16) ? A0 : A1;
        int ak = (ci & 15) * 32;
#pragma unroll
        for (int i = 0; i < 4; i++){
            int e = tid + i*256;
            int pl = e >> 9, r = (e >> 2) & 127, sg = e & 3;
            cpa16(bu + pl*RTILEA + (r*APITCH + sg*8)*2,
                  As + (long)r*1024 + (pl ? 512+ak : ak) + sg*8);
        }
        {
            int pl = tid >> 7, r = (tid >> 2) & 31, sg = tid & 3;
            if (r < NT)
                cpa16(bu + 2*RTILEA + pl*RTILEW + (r*APITCH + sg*8)*2,
                      Wp + (long)r*wstride + (pl ? wlo + ci*32 : ci*32) + sg*8);
        }
        cpa_commit();
    };

    int aoff = ((wid*16 + (lane & 15))*APITCH + (lane >> 4)*8) * 2;
    int boff = (((lane & 7) + ((lane >> 4) << 3))*APITCH + ((lane >> 3) & 1)*8) * 2;

    ld(0, 0);
    for (int ci = 0; ci < NCH; ci++){
        if (ci + 1 < NCH){ ld(ci+1, (ci+1) & 1); cpa_wait<1>(); }
        else             { cpa_wait<0>(); }
        __syncthreads();
        uint32_t bu = sbase + (ci & 1)*RBUF;
#pragma unroll
        for (int ks = 0; ks < 2; ks++){
            uint32_t ah[4], al[4];
            ldx4(ah, bu + aoff + ks*32);
            ldx4(al, bu + RTILEA + aoff + ks*32);
#pragma unroll
            for (int g = 0; g < NT/16; g++){
                uint32_t bh[4], bl[4];
                uint32_t bo = boff + g*16*APITCH*2 + ks*32;
                ldx4(bh, bu + 2*RTILEA + bo);
                ldx4(bl, bu + 2*RTILEA + RTILEW + bo);
                mma16816(acc[g*2+0], ah, bh[0], bh[1]);
                mma16816(acc[g*2+1], ah, bh[2], bh[3]);
                mma16816(acc[g*2+0], al, bh[0], bh[1]);
                mma16816(acc[g*2+1], al, bh[2], bh[3]);
                mma16816(acc[g*2+0], ah, bl[0], bl[1]);
                mma16816(acc[g*2+1], ah, bl[2], bl[3]);
            }
        }
        __syncthreads();
    }
}

// ---------------- persistent recurrent kernel (tensor-core) -----------------
__global__ void __launch_bounds__(256, 1)
k_recurrentT(const float* __restrict__ bu1, const float* __restrict__ br1,
             const float* __restrict__ bc1)
{
    extern __shared__ __align__(16) char dsmR[];
    uint32_t sbase = smem_u32(dsmR);
    int tid = threadIdx.x, wid = tid >> 5, lane = tid & 31, c = blockIdx.x;
    unsigned my_gen = 0;
    int gate = c >> 4, an0 = (c & 15) * 32;   // phases A/C
    int bn0 = c * 16;                          // phases B/D
    int lr = lane >> 2, lc = (lane & 3) * 2;

    const __nv_bfloat16* W0u = g_W0s + (long)0*512*1024 + (long)an0*1024;
    const __nv_bfloat16* W0r = g_W0s + (long)1*512*1024 + (long)an0*1024;
    const __nv_bfloat16* W0c = g_W0s + (long)2*512*1024 + (long)bn0*1024;
    const __nv_bfloat16* W1u = g_W1s + (long)0*512*2048 + (long)an0*2048;
    const __nv_bfloat16* W1r = g_W1s + (long)1*512*2048 + (long)an0*2048;
    const __nv_bfloat16* W1c = g_W1s + (long)2*512*2048 + (long)bn0*2048;

    for (int t = 0; t < TT; t++){
        const float* h0prev = (t == 0) ? g_h0 : ((t & 1) ? g_H0a : g_H0b);
        float*       h0cur  = (t & 1) ? g_H0b : g_H0a;
        const float* h1prev = (t == 0) ? g_h0 : g_H1 + (t-1)*BB*HH;
        float*       h1cur  = g_H1 + t*BB*HH;
        const float* XU = g_XU + t*BB*HH;
        const float* XR = g_XR + t*BB*HH;
        const float* XC = g_XC + t*BB*HH;
        const __nv_bfloat16* h1sprev = (t == 0) ? g_h0s
                                                : g_A2 + (long)(t-1)*128*1024;

        // --- Phase A: u0 / r0 gates (K=512, A=h0prev split) ---
        {
            float acc[4][4];
            mma_phaseR<32,16>(sbase, tid, wid, lane, g_H0s, g_H0s,
                              gate ? W0r : W0u, 1024, 512, acc);
#pragma unroll
            for (int g = 0; g < 4; g++){
                int n = an0 + g*8 + lc;
#pragma unroll
                for (int v = 0; v < 4; v++){
                    int row = wid*16 + lr + ((v >> 1) ? 8 : 0);
                    int col = n + (v & 1);
                    int idx = row*HH + col;
                    float val = acc[g][v];
                    if (gate == 0){
                        __stcg(&g_u[idx], sigmoidf_(val + XU[idx]));
                    } else {
                        float r_ = sigmoidf_(val + XR[idx]);
                        float rh = r_ * __ldcg(&h0prev[idx]);
                        __nv_bfloat16 hi = __float2bfloat16(rh);
                        __nv_bfloat16 lo = __float2bfloat16(rh - __bfloat162float(hi));
                        g_rhs[row*1024 + col]       = hi;
                        g_rhs[row*1024 + 512 + col] = lo;
                    }
                }
            }
        }
        gsyncN(my_gen);

        // --- Phase B: c0 + blend (K=512, A=rh split) ---
        {
            float acc[2][4];
            mma_phaseR<16,16>(sbase, tid, wid, lane, g_rhs, g_rhs,
                              W0c, 1024, 512, acc);
#pragma unroll
            for (int g = 0; g < 2; g++){
                int n = bn0 + g*8 + lc;
#pragma unroll
                for (int v = 0; v < 4; v++){
                    int row = wid*16 + lr + ((v >> 1) ? 8 : 0);
                    int col = n + (v & 1);
                    int idx = row*HH + col;
                    float c0 = tanhf(acc[g][v] + XC[idx]);
                    float uu = __ldcg(&g_u[idx]);
                    float hp = __ldcg(&h0prev[idx]);
                    float hn = uu*hp + (1.f - uu)*c0;
                    __stcg(&h0cur[idx], hn);
                    __nv_bfloat16 hi = __float2bfloat16(hn);
                    __nv_bfloat16 lo = __float2bfloat16(hn - __bfloat162float(hi));
                    g_H0s[row*1024 + col]       = hi;
                    g_H0s[row*1024 + 512 + col] = lo;
                }
            }
        }
        gsyncN(my_gen);

        // --- Phase C: u1 / r1 gates (K=1024, A=[h0cur | h1prev] split) ---
        {
            float acc[4][4];
            mma_phaseR<32,32>(sbase, tid, wid, lane, g_H0s, h1sprev,
                              gate ? W1r : W1u, 2048, 1024, acc);
#pragma unroll
            for (int g = 0; g < 4; g++){
                int n = an0 + g*8 + lc;
#pragma unroll
                for (int v = 0; v < 4; v++){
                    int row = wid*16 + lr + ((v >> 1) ? 8 : 0);
                    int col = n + (v & 1);
                    int idx = row*HH + col;
                    float val = acc[g][v];
                    if (gate == 0){
                        __stcg(&g_u[idx], sigmoidf_(val + bu1[col]));
                    } else {
                        float r_ = sigmoidf_(val + br1[col]);
                        float rh = r_ * __ldcg(&h1prev[idx]);
                        __nv_bfloat16 hi = __float2bfloat16(rh);
                        __nv_bfloat16 lo = __float2bfloat16(rh - __bfloat162float(hi));
                        g_rhs[row*1024 + col]       = hi;
                        g_rhs[row*1024 + 512 + col] = lo;
                    }
                }
            }
        }
        gsyncN(my_gen);

        // --- Phase D: c1 + blend (K=1024, A=[h0cur | rh1] split) ---
        {
            float acc[2][4];
            mma_phaseR<16,32>(sbase, tid, wid, lane, g_H0s, g_rhs,
                              W1c, 2048, 1024, acc);
            __nv_bfloat16* a2 = g_A2 + (long)t*128*1024;
#pragma unroll
            for (int g = 0; g < 2; g++){
                int n = bn0 + g*8 + lc;
#pragma unroll
                for (int v = 0; v < 4; v++){
                    int row = wid*16 + lr + ((v >> 1) ? 8 : 0);
                    int col = n + (v & 1);
                    int idx = row*HH + col;
                    float c1 = tanhf(acc[g][v] + bc1[col]);
                    float uu = __ldcg(&g_u[idx]);
                    float hp = __ldcg(&h1prev[idx]);
                    float hn = uu*hp + (1.f - uu)*c1;
                    __stcg(&h1cur[idx], hn);
                    __nv_bfloat16 hi = __float2bfloat16(hn);
                    __nv_bfloat16 lo = __float2bfloat16(hn - __bfloat162float(hi));
                    a2[row*1024 + col]       = hi;
                    a2[row*1024 + 512 + col] = lo;
                }
            }
        }
        gsyncN(my_gen);
    }
}

// ---------------- final state copy ------------------------------------------
__global__ void k_copy_final(const float* __restrict__ h0f,
                             const float* __restrict__ h1f,
                             float* __restrict__ out)
{
    int i = blockIdx.x * blockDim.x + threadIdx.x;
    if (i < BB*HH){
        out[i]         = h0f[i];
        out[BB*HH + i] = h1f[i];
    }
}

// ---------------- launch ----------------------------------------------------
extern "C" void kernel_launch(void* const* d_in, const int* in_sizes, int n_in,
                              void* d_out, int out_size)
{
    const float* cnn = (const float*)d_in[0];
    const int*   tok = (const int*)  d_in[1];
    const float* emb = (const float*)d_in[2];
    const float* inW = (const float*)d_in[3];
    const float* inb = (const float*)d_in[4];
    const float* Wu0 = (const float*)d_in[5];
    const float* bu0 = (const float*)d_in[6];
    const float* Wr0 = (const float*)d_in[7];
    const float* br0 = (const float*)d_in[8];
    const float* Wc0 = (const float*)d_in[9];
    const float* bc0 = (const float*)d_in[10];
    const float* Wu1 = (const float*)d_in[11];
    const float* bu1 = (const float*)d_in[12];
    const float* Wr1 = (const float*)d_in[13];
    const float* br1 = (const float*)d_in[14];
    const float* Wc1 = (const float*)d_in[15];
    const float* bc1 = (const float*)d_in[16];
    const float* outW= (const float*)d_in[17];
    const float* outb= (const float*)d_in[18];
    float* out = (float*)d_out;

    float *ph0,*pemb,*pXU,*pXR,*pXC,*pH0b,*pH1;
    __nv_bfloat16 *pW0s, *pW1s;
    cudaGetSymbolAddress((void**)&ph0,  g_h0);
    cudaGetSymbolAddress((void**)&pemb, g_emb);
    cudaGetSymbolAddress((void**)&pXU,  g_XU);
    cudaGetSymbolAddress((void**)&pXR,  g_XR);
    cudaGetSymbolAddress((void**)&pXC,  g_XC);
    cudaGetSymbolAddress((void**)&pH0b, g_H0b);
    cudaGetSymbolAddress((void**)&pH1,  g_H1);
    cudaGetSymbolAddress((void**)&pW0s, g_W0s);
    cudaGetSymbolAddress((void**)&pW1s, g_W1s);

    cudaFuncSetAttribute(k_logits_mma, cudaFuncAttributeMaxDynamicSharedMemorySize, 2*BUFB);
    cudaFuncSetAttribute(k_recurrentT, cudaFuncAttributeMaxDynamicSharedMemorySize, RSMEM);

    // h0 = tanh(cnn @ in_W + in_b)
    k_gemmL<1><<<dim3(8, 1), 256>>>(cnn, inW, inb, ph0, 128, 512, 2048, 2048, 512, 512);
    // gather embeddings
    k_gather<<<TT*BB, 128>>>(tok, emb);
    // logits-weight split
    k_packB<<<dim3(VPAD/64, 16), 256>>>(outW);
    // recurrent-weight splits (h-part of layer0, full layer1)
    const float* Wu0h = Wu0 + (long)EE*HH;
    const float* Wr0h = Wr0 + (long)EE*HH;
    const float* Wc0h = Wc0 + (long)EE*HH;
    k_packW<<<dim3(8, 16), 256>>>(Wu0h, pW0s + (long)0*512*1024, 512);
    k_packW<<<dim3(8, 16), 256>>>(Wr0h, pW0s + (long)1*512*1024, 512);
    k_packW<<<dim3(8, 16), 256>>>(Wc0h, pW0s + (long)2*512*1024, 512);
    k_packW<<<dim3(8, 32), 256>>>(Wu1,  pW1s + (long)0*512*2048, 1024);
    k_packW<<<dim3(8, 32), 256>>>(Wr1,  pW1s + (long)1*512*2048, 1024);
    k_packW<<<dim3(8, 32), 256>>>(Wc1,  pW1s + (long)2*512*2048, 1024);
    // layer-0 x-projections for ALL timesteps
    k_gemmL<0><<<dim3(8, 32), 256>>>(pemb, Wu0, bu0, pXU, 4096, 512, 512, 512, 512, 512);
    k_gemmL<0><<<dim3(8, 32), 256>>>(pemb, Wr0, br0, pXR, 4096, 512, 512, 512, 512, 512);
    k_gemmL<0><<<dim3(8, 32), 256>>>(pemb, Wc0, bc0, pXC, 4096, 512, 512, 512, 512, 512);
    // h0 split
    k_splitH0<<<BB*HH/256, 256>>>();

    // persistent tensor-core recurrent kernel
    k_reset<<<1, 1>>>();
    k_recurrentT<<<NCTA_R, 256, RSMEM>>>(bu1, br1, bc1);

    // logits (g_A2 filled directly by phase D)
    k_logits_mma<<<dim3(VPAD/128, 32), 256, 2*BUFB>>>(outb, out);

    // final_state (t=31 odd -> g_H0b holds layer0 final)
    k_copy_final<<<(BB*HH + 255)/256, 256>>>(pH0b, pH1 + (long)(TT-1)*BB*HH,
                                             out + (long)BB*TT*VV);
}

// round 8
// speedup vs baseline: 1.7121x; 1.7121x over previous
#include <cuda_runtime.h>
#include <cuda_bf16.h>
#include <cstdint>
#include <stdint.h>
#include <math.h>

#define BB 128
#define TT 32
#define EE 512
#define HH 512
#define VV 10000
#define CF 2048
#define VPAD 10112            // 79 n-tiles of 128

#define APITCH 40             // logits smem pitch (80B, conflict-free)
#define TILEB (128*APITCH*2)
#define BUFB (4*TILEB)

#define NCTA_R 128

typedef unsigned long long ull;

// ---------------- scratch (device globals; no allocations allowed) ----------
__device__ float g_h0[BB*HH];
__device__ float g_emb[TT*BB*EE];
__device__ float g_XU[TT*BB*HH];
__device__ float g_XR[TT*BB*HH];
__device__ float g_XC[TT*BB*HH];
__device__ float g_H0a[BB*HH];
__device__ float g_H0b[BB*HH];
__device__ float g_H1[TT*BB*HH];
__device__ float g_u[BB*HH];
__device__ unsigned g_bar;
__device__ unsigned g_gen;
// logits buffers (row = [hi512|lo512], R6 layout)
__device__ __nv_bfloat16 g_A2[4096*1024];
__device__ __nv_bfloat16 g_B2[VPAD*1024];
// fragment-packed buffers: tile = 32 lanes x 16B; A-type: [mt8][kt32][pl2][lane32]
__device__ uint4 g_H0sF[16384];
__device__ uint4 g_h0sF[16384];
__device__ uint4 g_rhsF[16384];
__device__ uint4 g_H1sF[16384];
// weight frags: [gate][nt32][kt][pl2][lane32]; W0 kt=32 (1MB/gate), W1 kt=64
__device__ uint4 g_W0F[3*65536];
__device__ uint4 g_W1F[3*131072];

__device__ __forceinline__ float sigmoidf_(float v){ return 1.f/(1.f+__expf(-v)); }

// packed f32x2 helpers (FFMA2 prep GEMMs)
__device__ __forceinline__ void fma2(ull &acc, ull a, ull b){
    asm("fma.rn.f32x2 %0, %1, %2, %0;" : "+l"(acc) : "l"(a), "l"(b));
}
__device__ __forceinline__ ull dup2(float x){
    ull r; asm("mov.b64 %0, {%1, %1};" : "=l"(r) : "f"(x)); return r;
}
__device__ __forceinline__ float2 unp2(ull v){
    float2 f; asm("mov.b64 {%0, %1}, %2;" : "=f"(f.x), "=f"(f.y) : "l"(v)); return f;
}

// ---------------- mma helpers ------------------------------------------------
__device__ __forceinline__ uint32_t smem_u32(const void* p){
    uint32_t a;
    asm("{ .reg .u64 t; cvta.to.shared.u64 t, %1; cvt.u32.u64 %0, t; }" : "=r"(a) : "l"(p));
    return a;
}
__device__ __forceinline__ void cpa16(uint32_t dst, const void* src){
    asm volatile("cp.async.cg.shared.global [%0], [%1], 16;" :: "r"(dst), "l"(src));
}
__device__ __forceinline__ void cpa_commit(){
    asm volatile("cp.async.commit_group;" ::: "memory");
}
template<int N> __device__ __forceinline__ void cpa_wait(){
    asm volatile("cp.async.wait_group %0;" :: "n"(N) : "memory");
}
__device__ __forceinline__ void ldx4(uint32_t* r, uint32_t addr){
    asm volatile("ldmatrix.sync.aligned.m8n8.x4.shared.b16 {%0,%1,%2,%3}, [%4];"
        : "=r"(r[0]), "=r"(r[1]), "=r"(r[2]), "=r"(r[3]) : "r"(addr));
}
__device__ __forceinline__ void mma16816(float* d, const uint32_t* a,
                                         uint32_t b0, uint32_t b1){
    asm volatile("mma.sync.aligned.m16n8k16.row.col.f32.bf16.bf16.f32 "
        "{%0,%1,%2,%3}, {%4,%5,%6,%7}, {%8,%9}, {%0,%1,%2,%3};"
        : "+f"(d[0]), "+f"(d[1]), "+f"(d[2]), "+f"(d[3])
        : "r"(a[0]), "r"(a[1]), "r"(a[2]), "r"(a[3]), "r"(b0), "r"(b1));
}
__device__ __forceinline__ void mmaU(float* d, const uint4 &a, uint32_t b0, uint32_t b1){
    asm volatile("mma.sync.aligned.m16n8k16.row.col.f32.bf16.bf16.f32 "
        "{%0,%1,%2,%3}, {%4,%5,%6,%7}, {%8,%9}, {%0,%1,%2,%3};"
        : "+f"(d[0]), "+f"(d[1]), "+f"(d[2]), "+f"(d[3])
        : "r"(a.x), "r"(a.y), "r"(a.z), "r"(a.w), "r"(b0), "r"(b1));
}

// split/pack helpers
__device__ __forceinline__ uint32_t bfpair(float a, float b){
    __nv_bfloat162 t = __floats2bfloat162_rn(a, b);
    return *reinterpret_cast<uint32_t*>(&t);
}
__device__ __forceinline__ float bfres(float a){
    return a - __bfloat162float(__float2bfloat16(a));
}
// v[g][0..3] = values at (r,cg),(r,cg+1),(r+8,cg),(r+8,cg+1) for groups g=0,1
__device__ __forceinline__ void store_frag(uint4* dst, const float v[2][4]){
    uint4 HI, LO;
    HI.x = bfpair(v[0][0], v[0][1]); HI.y = bfpair(v[0][2], v[0][3]);
    HI.z = bfpair(v[1][0], v[1][1]); HI.w = bfpair(v[1][2], v[1][3]);
    LO.x = bfpair(bfres(v[0][0]), bfres(v[0][1]));
    LO.y = bfpair(bfres(v[0][2]), bfres(v[0][3]));
    LO.z = bfpair(bfres(v[1][0]), bfres(v[1][1]));
    LO.w = bfpair(bfres(v[1][2]), bfres(v[1][3]));
    __stcg(dst, HI);
    __stcg(dst + 32, LO);
}

// ---------------- embedding gather ------------------------------------------
__global__ void k_gather(const int* __restrict__ tok, const float* __restrict__ emb){
    int row = blockIdx.x;            // t*BB + b
    int t = row >> 7, b = row & 127;
    int v = tok[b*TT + t];
    const float4* src = (const float4*)(emb + (long)v*EE);
    float4* dst = (float4*)(g_emb + (long)row*EE);
    dst[threadIdx.x] = src[threadIdx.x];
}

// ---------------- big fp32 GEMM, 128x64 tile, FFMA2 (prep + h0) -------------
template<int EPI>
__global__ void __launch_bounds__(256)
k_gemmL(const float* __restrict__ A, const float* __restrict__ Bm,
        const float* __restrict__ bias, float* __restrict__ C,
        int M, int N, int K, int lda, int ldb, int ldc)
{
    __shared__ __align__(16) float As[16*132];
    __shared__ __align__(16) float Bs[16*68];
    int tid = threadIdx.x;
    int ty = tid >> 4, tx = tid & 15;
    int m0 = blockIdx.y * 128, n0 = blockIdx.x * 64;
    int ar = tid >> 1, ac = (tid & 1) * 8;
    int br = tid >> 4, bc = (tid & 15) * 4;
    bool bok = (n0 + bc) < N;

    ull acc[4][4] = {};
    float4 a0, a1, b0;

    a0 = *(const float4*)(A + (long)(m0+ar)*lda + ac);
    a1 = *(const float4*)(A + (long)(m0+ar)*lda + ac + 4);
    b0 = bok ? *(const float4*)(Bm + (long)br*ldb + n0 + bc)
             : make_float4(0.f,0.f,0.f,0.f);
    As[(ac+0)*132+ar]=a0.x; As[(ac+1)*132+ar]=a0.y; As[(ac+2)*132+ar]=a0.z; As[(ac+3)*132+ar]=a0.w;
    As[(ac+4)*132+ar]=a1.x; As[(ac+5)*132+ar]=a1.y; As[(ac+6)*132+ar]=a1.z; As[(ac+7)*132+ar]=a1.w;
    *(float4*)&Bs[br*68+bc] = b0;
    __syncthreads();

    int nch = K >> 4;
    for (int ch = 1; ch <= nch; ch++){
        if (ch < nch){
            int k0 = ch * 16;
            a0 = *(const float4*)(A + (long)(m0+ar)*lda + k0 + ac);
            a1 = *(const float4*)(A + (long)(m0+ar)*lda + k0 + ac + 4);
            b0 = bok ? *(const float4*)(Bm + (long)(k0+br)*ldb + n0 + bc)
                     : make_float4(0.f,0.f,0.f,0.f);
        }
#pragma unroll
        for (int kk = 0; kk < 16; kk++){
            ull av[4];
#pragma unroll
            for (int p = 0; p < 4; p++)
                av[p] = *(const ull*)(As + kk*132 + ty*8 + 2*p);
            float4 bv = *(const float4*)(Bs + kk*68 + tx*4);
            ull bb0 = dup2(bv.x), bb1 = dup2(bv.y), bb2 = dup2(bv.z), bb3 = dup2(bv.w);
#pragma unroll
            for (int p = 0; p < 4; p++){
                fma2(acc[p][0], av[p], bb0);
                fma2(acc[p][1], av[p], bb1);
                fma2(acc[p][2], av[p], bb2);
                fma2(acc[p][3], av[p], bb3);
            }
        }
        if (ch < nch){
            __syncthreads();
            As[(ac+0)*132+ar]=a0.x; As[(ac+1)*132+ar]=a0.y; As[(ac+2)*132+ar]=a0.z; As[(ac+3)*132+ar]=a0.w;
            As[(ac+4)*132+ar]=a1.x; As[(ac+5)*132+ar]=a1.y; As[(ac+6)*132+ar]=a1.z; As[(ac+7)*132+ar]=a1.w;
            *(float4*)&Bs[br*68+bc] = b0;
            __syncthreads();
        }
    }

#pragma unroll
    for (int p = 0; p < 4; p++){
#pragma unroll
        for (int j = 0; j < 4; j++){
            float2 v = unp2(acc[p][j]);
            int n = n0 + tx*4 + j;
            if (n < N){
                float bz = bias[n];
                float r0 = v.x + bz, r1 = v.y + bz;
                if (EPI == 1){ r0 = tanhf(r0); r1 = tanhf(r1); }
                int row0 = ty*8 + 2*p;
                C[(long)(m0+row0)*ldc + n] = r0;
                C[(long)(m0+row0+1)*ldc + n] = r1;
            }
        }
    }
}

// ---------------- packers ---------------------------------------------------
// out_W [512,10000] -> g_B2 [VPAD rows][hi512|lo512] (logits, row-major)
__global__ void k_packB(const float* __restrict__ W){
    __shared__ float tile[32][65];
    int n0 = blockIdx.x * 64, k0 = blockIdx.y * 32;
    int tid = threadIdx.x;
#pragma unroll
    for (int p = 0; p < 8; p++){
        int idx = tid + p*256;
        int kk = idx >> 6, nn = idx & 63;
        int n = n0 + nn;
        tile[kk][nn] = (n < VV) ? W[(long)(k0+kk)*VV + n] : 0.f;
    }
    __syncthreads();
#pragma unroll
    for (int p = 0; p < 8; p++){
        int idx = tid + p*256;
        int nn = idx >> 5, kk = idx & 31;
        float v = tile[kk][nn];
        __nv_bfloat16 hi = __float2bfloat16(v);
        __nv_bfloat16 lo = __float2bfloat16(v - __bfloat162float(hi));
        long base = (long)(n0+nn)*1024 + k0 + kk;
        g_B2[base]       = hi;
        g_B2[base + 512] = lo;
    }
}

// weight W [K,512] -> frag layout [nt][kt][pl][lane] (B-fragment word order)
__global__ void k_packWF(const float* __restrict__ W, uint4* __restrict__ dst, int KT){
    int nt = blockIdx.x, kt = blockIdx.y, l = threadIdx.x;
    int n0 = nt*16 + (l >> 2), k0 = kt*16 + (l & 3)*2;
    float v[2][4];
    v[0][0] = W[(long)(k0  )*HH + n0];   v[0][1] = W[(long)(k0+1)*HH + n0];
    v[0][2] = W[(long)(k0+8)*HH + n0];   v[0][3] = W[(long)(k0+9)*HH + n0];
    v[1][0] = W[(long)(k0  )*HH + n0+8]; v[1][1] = W[(long)(k0+1)*HH + n0+8];
    v[1][2] = W[(long)(k0+8)*HH + n0+8]; v[1][3] = W[(long)(k0+9)*HH + n0+8];
    store_frag(dst + (long)((nt*KT + kt)*2)*32 + l, v);
}

// split initial h0 -> A-fragment buffers g_H0sF + g_h0sF
__global__ void k_splitH0F(){
    int mt = blockIdx.x, kt = blockIdx.y, l = threadIdx.x;
    int m0 = mt*16 + (l >> 2), k0 = kt*16 + (l & 3)*2;
    float v[2][4];
    v[0][0] = g_h0[(m0  )*HH + k0];   v[0][1] = g_h0[(m0  )*HH + k0+1];
    v[0][2] = g_h0[(m0+8)*HH + k0];   v[0][3] = g_h0[(m0+8)*HH + k0+1];
    v[1][0] = g_h0[(m0  )*HH + k0+8]; v[1][1] = g_h0[(m0  )*HH + k0+9];
    v[1][2] = g_h0[(m0+8)*HH + k0+8]; v[1][3] = g_h0[(m0+8)*HH + k0+9];
    int off = (mt*32 + kt)*64 + l;
    store_frag(&g_H0sF[0] + off, v);
    store_frag(&g_h0sF[0] + off, v);
}

// ---------------- logits GEMM (R6, unchanged) -------------------------------
__global__ void __launch_bounds__(256)
k_logits_mma(const float* __restrict__ bias, float* __restrict__ out)
{
    extern __shared__ __align__(16) char dsm[];
    int tid = threadIdx.x, lane = tid & 31, wid = tid >> 5;
    int t = blockIdx.y;
    int n0 = blockIdx.x * 128;
    int wm = (wid & 1) * 64, wn = (wid >> 1) * 32;

    const __nv_bfloat16* Abase = g_A2 + (long)t*128*1024;
    const __nv_bfloat16* Bbase = g_B2 + (long)n0*1024;
    uint32_t sbase = smem_u32(dsm);

    float acc[4][4][4];
#pragma unroll
    for (int i = 0; i < 4; i++)
#pragma unroll
        for (int j = 0; j < 4; j++)
#pragma unroll
            for (int q = 0; q < 4; q++) acc[i][j][q] = 0.f;

    int aoff = (wm + (lane & 15)) * APITCH + (lane >> 4) * 8;
    int boff = (wn + (lane & 7) + ((lane >> 4) << 3)) * APITCH + ((lane >> 3) & 1) * 8;

    auto load_chunk = [&](int c, int bi){
        int k0 = c * 32;
        uint32_t bu = sbase + bi * BUFB;
#pragma unroll
        for (int it = 0; it < 8; it++){
            int e = tid + it * 256;
            int tile = e >> 9;
            int r = (e >> 2) & 127;
            int seg = e & 3;
            const __nv_bfloat16* src =
                (tile < 2 ? Abase : Bbase) + (long)r*1024 + ((tile & 1) ? 512 : 0) + k0 + seg*8;
            cpa16(bu + tile*TILEB + (r*APITCH + seg*8)*2, src);
        }
        cpa_commit();
    };

    load_chunk(0, 0);
    for (int c = 0; c < 16; c++){
        if (c + 1 < 16){ load_chunk(c+1, (c+1) & 1); cpa_wait<1>(); }
        else           { cpa_wait<0>(); }
        __syncthreads();
        uint32_t bu = sbase + (c & 1) * BUFB;
        uint32_t uAh = bu, uAl = bu + TILEB, uBh = bu + 2*TILEB, uBl = bu + 3*TILEB;
#pragma unroll
        for (int ks = 0; ks < 2; ks++){
            uint32_t ah[4][4], al[4][4], bh[2][4], bl[2][4];
#pragma unroll
            for (int mi = 0; mi < 4; mi++){
                uint32_t ao = (uint32_t)(aoff + mi*16*APITCH + ks*16) * 2;
                ldx4(ah[mi], uAh + ao);
                ldx4(al[mi], uAl + ao);
            }
#pragma unroll
            for (int p = 0; p < 2; p++){
                uint32_t bo = (uint32_t)(boff + p*16*APITCH + ks*16) * 2;
                ldx4(bh[p], uBh + bo);
                ldx4(bl[p], uBl + bo);
            }
#pragma unroll
            for (int mi = 0; mi < 4; mi++)
#pragma unroll
                for (int nj = 0; nj < 4; nj++){
                    int p = nj >> 1, q = (nj & 1) * 2;
                    mma16816(acc[mi][nj], ah[mi], bh[p][q], bh[p][q+1]);
                    mma16816(acc[mi][nj], al[mi], bh[p][q], bh[p][q+1]);
                    mma16816(acc[mi][nj], ah[mi], bl[p][q], bl[p][q+1]);
                }
        }
        __syncthreads();
    }

    int lr = lane >> 2, lc = (lane & 3) * 2;
    long strideB = TT * (long)VV;
#pragma unroll
    for (int mi = 0; mi < 4; mi++){
        int b0 = wm + mi*16 + lr;
        long base0 = (long)b0*strideB + (long)t*VV;
#pragma unroll
        for (int nj = 0; nj < 4; nj++){
            int n = n0 + wn + nj*8 + lc;
            const float* a4 = acc[mi][nj];
            if (n < VV){
                float bz = bias[n];
                out[base0 + n]               = a4[0] + bz;
                out[base0 + 8*strideB + n]   = a4[2] + bz;
            }
            if (n + 1 < VV){
                float bz = bias[n+1];
                out[base0 + n + 1]             = a4[1] + bz;
                out[base0 + 8*strideB + n + 1] = a4[3] + bz;
            }
        }
    }
}

// ---------------- barrier reset + grid barrier ------------------------------
__global__ void k_reset(){ g_bar = 0u; g_gen = 0u; }

__device__ __forceinline__ void gsyncN(unsigned &my_gen){
    __syncthreads();
    if (threadIdx.x == 0){
        __threadfence();
        my_gen++;
        if (atomicAdd(&g_bar, 1u) == NCTA_R-1u){
            atomicExch(&g_bar, 0u);
            __threadfence();
            atomicExch(&g_gen, my_gen);
        } else {
            while (*(volatile unsigned*)&g_gen < my_gen) { }
            __threadfence();
        }
    }
    __syncthreads();
}

// ---------------- register-direct fragment GEMM -----------------------------
// A0/A1: A-frag bases (tile stride 64 uint4, plane +32), kt<32 -> A0 else A1.
// Wb: W-frag base (tile stride 64). acc[2][4] = two n8 groups.
template<int KT>
__device__ __forceinline__ void frag_mm(const uint4* __restrict__ A0,
                                        const uint4* __restrict__ A1,
                                        const uint4* __restrict__ Wb,
                                        float acc[2][4])
{
#pragma unroll
    for (int g = 0; g < 2; g++)
#pragma unroll
        for (int q = 0; q < 4; q++) acc[g][q] = 0.f;

    uint4 cAh = __ldcg(A0), cAl = __ldcg(A0 + 32);
    uint4 cWh = Wb[0], cWl = Wb[32];
#pragma unroll 4
    for (int kt = 0; kt < KT; kt++){
        uint4 nAh, nAl, nWh, nWl;
        if (kt + 1 < KT){
            const uint4* an = ((kt+1) < 32) ? (A0 + (kt+1)*64) : (A1 + (kt+1-32)*64);
            nAh = __ldcg(an); nAl = __ldcg(an + 32);
            nWh = Wb[(kt+1)*64]; nWl = Wb[(kt+1)*64 + 32];
        } else { nAh = cAh; nAl = cAl; nWh = cWh; nWl = cWl; }
        mmaU(acc[0], cAh, cWh.x, cWh.y); mmaU(acc[1], cAh, cWh.z, cWh.w);
        mmaU(acc[0], cAl, cWh.x, cWh.y); mmaU(acc[1], cAl, cWh.z, cWh.w);
        mmaU(acc[0], cAh, cWl.x, cWl.y); mmaU(acc[1], cAh, cWl.z, cWl.w);
        cAh = nAh; cAl = nAl; cWh = nWh; cWl = nWl;
    }
}

// ---------------- persistent recurrent kernel (fragment mma) ----------------
__global__ void __launch_bounds__(128, 1)
k_recurrentF(const float* __restrict__ bu1, const float* __restrict__ br1,
             const float* __restrict__ bc1)
{
    int tid = threadIdx.x, w = tid >> 5, lane = tid & 31;
    int gw = blockIdx.x * 4 + w;            // 0..511
    int lr = lane >> 2, lc2 = (lane & 3) * 2;
    unsigned my_gen = 0;

    // phase A/C: gate x nt x mt, warps in a CTA share nt (W L1 reuse)
    int gate = gw >> 8;
    int ntA  = (gw >> 3) & 31;
    int mtA  = gw & 7;
    // phase B/D: half the warps active
    bool actBD = (gw & 1) == 0;
    int u2  = gw >> 1;
    int ntB = (u2 >> 3) & 31;
    int mtB = u2 & 7;

    const uint4* WA0 = &g_W0F[0] + (long)gate*65536 + ntA*2048 + lane;      // u/r L0
    const uint4* WB0 = &g_W0F[0] + (long)2*65536   + ntB*2048 + lane;      // c L0
    const uint4* WA1 = &g_W1F[0] + (long)gate*131072 + ntA*4096 + lane;    // u/r L1
    const uint4* WB1 = &g_W1F[0] + (long)2*131072   + ntB*4096 + lane;     // c L1

    for (int t = 0; t < TT; t++){
        const float* h0prev = (t == 0) ? g_h0 : ((t & 1) ? g_H0a : g_H0b);
        float*       h0cur  = (t & 1) ? g_H0b : g_H0a;
        const float* h1prev = (t == 0) ? g_h0 : g_H1 + (t-1)*BB*HH;
        float*       h1cur  = g_H1 + t*BB*HH;
        const float* XU = g_XU + t*BB*HH;
        const float* XR = g_XR + t*BB*HH;
        const float* XC = g_XC + t*BB*HH;
        const uint4* h1sF = ((t == 0) ? &g_h0sF[0] : &g_H1sF[0]);

        // --- Phase A: u0 / r0 (K=512, A = h0prev frags) ---
        {
            float acc[2][4];
            const uint4* A0 = &g_H0sF[0] + mtA*2048 + lane;
            frag_mm<32>(A0, A0, WA0, acc);
            int r0 = mtA*16 + lr;
            if (gate == 0){
#pragma unroll
                for (int g = 0; g < 2; g++){
                    int cg = ntA*16 + g*8 + lc2;
                    int i0 = r0*HH + cg, i1 = (r0+8)*HH + cg;
                    __stcg(&g_u[i0],   sigmoidf_(acc[g][0] + XU[i0]));
                    __stcg(&g_u[i0+1], sigmoidf_(acc[g][1] + XU[i0+1]));
                    __stcg(&g_u[i1],   sigmoidf_(acc[g][2] + XU[i1]));
                    __stcg(&g_u[i1+1], sigmoidf_(acc[g][3] + XU[i1+1]));
                }
            } else {
                float vv[2][4];
#pragma unroll
                for (int g = 0; g < 2; g++){
                    int cg = ntA*16 + g*8 + lc2;
                    int i0 = r0*HH + cg, i1 = (r0+8)*HH + cg;
                    vv[g][0] = sigmoidf_(acc[g][0] + XR[i0])   * __ldcg(&h0prev[i0]);
                    vv[g][1] = sigmoidf_(acc[g][1] + XR[i0+1]) * __ldcg(&h0prev[i0+1]);
                    vv[g][2] = sigmoidf_(acc[g][2] + XR[i1])   * __ldcg(&h0prev[i1]);
                    vv[g][3] = sigmoidf_(acc[g][3] + XR[i1+1]) * __ldcg(&h0prev[i1+1]);
                }
                store_frag(&g_rhsF[0] + mtA*2048 + ntA*64 + lane, vv);
            }
        }
        gsyncN(my_gen);

        // --- Phase B: c0 + blend -> h0cur (K=512, A = rh frags) ---
        if (actBD){
            float acc[2][4];
            const uint4* A0 = &g_rhsF[0] + mtB*2048 + lane;
            frag_mm<32>(A0, A0, WB0, acc);
            int r0 = mtB*16 + lr;
            float vv[2][4];
#pragma unroll
            for (int g = 0; g < 2; g++){
                int cg = ntB*16 + g*8 + lc2;
                int idx[4] = { r0*HH + cg, r0*HH + cg + 1,
                               (r0+8)*HH + cg, (r0+8)*HH + cg + 1 };
#pragma unroll
                for (int j = 0; j < 4; j++){
                    float c0 = tanhf(acc[g][j] + XC[idx[j]]);
                    float uu = __ldcg(&g_u[idx[j]]);
                    float hp = __ldcg(&h0prev[idx[j]]);
                    float hn = uu*hp + (1.f - uu)*c0;
                    __stcg(&h0cur[idx[j]], hn);
                    vv[g][j] = hn;
                }
            }
            store_frag(&g_H0sF[0] + mtB*2048 + ntB*64 + lane, vv);
        }
        gsyncN(my_gen);

        // --- Phase C: u1 / r1 (K=1024, A = [h0cur | h1prev] frags) ---
        {
            float acc[2][4];
            const uint4* A0 = &g_H0sF[0] + mtA*2048 + lane;
            const uint4* A1 = h1sF + mtA*2048 + lane;
            frag_mm<64>(A0, A1, WA1, acc);
            int r0 = mtA*16 + lr;
            if (gate == 0){
#pragma unroll
                for (int g = 0; g < 2; g++){
                    int cg = ntA*16 + g*8 + lc2;
                    int i0 = r0*HH + cg, i1 = (r0+8)*HH + cg;
                    __stcg(&g_u[i0],   sigmoidf_(acc[g][0] + bu1[cg]));
                    __stcg(&g_u[i0+1], sigmoidf_(acc[g][1] + bu1[cg+1]));
                    __stcg(&g_u[i1],   sigmoidf_(acc[g][2] + bu1[cg]));
                    __stcg(&g_u[i1+1], sigmoidf_(acc[g][3] + bu1[cg+1]));
                }
            } else {
                float vv[2][4];
#pragma unroll
                for (int g = 0; g < 2; g++){
                    int cg = ntA*16 + g*8 + lc2;
                    int i0 = r0*HH + cg, i1 = (r0+8)*HH + cg;
                    vv[g][0] = sigmoidf_(acc[g][0] + br1[cg])   * __ldcg(&h1prev[i0]);
                    vv[g][1] = sigmoidf_(acc[g][1] + br1[cg+1]) * __ldcg(&h1prev[i0+1]);
                    vv[g][2] = sigmoidf_(acc[g][2] + br1[cg])   * __ldcg(&h1prev[i1]);
                    vv[g][3] = sigmoidf_(acc[g][3] + br1[cg+1]) * __ldcg(&h1prev[i1+1]);
                }
                store_frag(&g_rhsF[0] + mtA*2048 + ntA*64 + lane, vv);
            }
        }
        gsyncN(my_gen);

        // --- Phase D: c1 + blend -> h1cur (K=1024, A = [h0cur | rh1] frags) ---
        if (actBD){
            float acc[2][4];
            const uint4* A0 = &g_H0sF[0] + mtB*2048 + lane;
            const uint4* A1 = &g_rhsF[0] + mtB*2048 + lane;
            frag_mm<64>(A0, A1, WB1, acc);
            int r0 = mtB*16 + lr;
            float vv[2][4];
            __nv_bfloat16* a2 = g_A2 + (long)t*131072;
#pragma unroll
            for (int g = 0; g < 2; g++){
                int cg = ntB*16 + g*8 + lc2;
#pragma unroll
                for (int j = 0; j < 4; j++){
                    int row = r0 + ((j >> 1) ? 8 : 0);
                    int col = cg + (j & 1);
                    int idx = row*HH + col;
                    float c1 = tanhf(acc[g][j] + bc1[col]);
                    float uu = __ldcg(&g_u[idx]);
                    float hp = __ldcg(&h1prev[idx]);
                    float hn = uu*hp + (1.f - uu)*c1;
                    __stcg(&h1cur[idx], hn);
                    vv[g][j] = hn;
                    __nv_bfloat16 hi = __float2bfloat16(hn);
                    a2[row*1024 + col]       = hi;
                    a2[row*1024 + 512 + col] = __float2bfloat16(hn - __bfloat162float(hi));
                }
            }
            store_frag(&g_H1sF[0] + mtB*2048 + ntB*64 + lane, vv);
        }
        gsyncN(my_gen);
    }
}

// ---------------- final state copy ------------------------------------------
__global__ void k_copy_final(const float* __restrict__ h0f,
                             const float* __restrict__ h1f,
                             float* __restrict__ out)
{
    int i = blockIdx.x * blockDim.x + threadIdx.x;
    if (i < BB*HH){
        out[i]         = h0f[i];
        out[BB*HH + i] = h1f[i];
    }
}

// ---------------- launch ----------------------------------------------------
extern "C" void kernel_launch(void* const* d_in, const int* in_sizes, int n_in,
                              void* d_out, int out_size)
{
    const float* cnn = (const float*)d_in[0];
    const int*   tok = (const int*)  d_in[1];
    const float* emb = (const float*)d_in[2];
    const float* inW = (const float*)d_in[3];
    const float* inb = (const float*)d_in[4];
    const float* Wu0 = (const float*)d_in[5];
    const float* bu0 = (const float*)d_in[6];
    const float* Wr0 = (const float*)d_in[7];
    const float* br0 = (const float*)d_in[8];
    const float* Wc0 = (const float*)d_in[9];
    const float* bc0 = (const float*)d_in[10];
    const float* Wu1 = (const float*)d_in[11];
    const float* bu1 = (const float*)d_in[12];
    const float* Wr1 = (const float*)d_in[13];
    const float* br1 = (const float*)d_in[14];
    const float* Wc1 = (const float*)d_in[15];
    const float* bc1 = (const float*)d_in[16];
    const float* outW= (const float*)d_in[17];
    const float* outb= (const float*)d_in[18];
    float* out = (float*)d_out;

    float *ph0,*pemb,*pXU,*pXR,*pXC,*pH0b,*pH1;
    uint4 *pW0F, *pW1F;
    cudaGetSymbolAddress((void**)&ph0,  g_h0);
    cudaGetSymbolAddress((void**)&pemb, g_emb);
    cudaGetSymbolAddress((void**)&pXU,  g_XU);
    cudaGetSymbolAddress((void**)&pXR,  g_XR);
    cudaGetSymbolAddress((void**)&pXC,  g_XC);
    cudaGetSymbolAddress((void**)&pH0b, g_H0b);
    cudaGetSymbolAddress((void**)&pH1,  g_H1);
    cudaGetSymbolAddress((void**)&pW0F, g_W0F);
    cudaGetSymbolAddress((void**)&pW1F, g_W1F);

    cudaFuncSetAttribute(k_logits_mma, cudaFuncAttributeMaxDynamicSharedMemorySize, 2*BUFB);

    // h0 = tanh(cnn @ in_W + in_b)
    k_gemmL<1><<<dim3(8, 1), 256>>>(cnn, inW, inb, ph0, 128, 512, 2048, 2048, 512, 512);
    // gather embeddings
    k_gather<<<TT*BB, 128>>>(tok, emb);
    // logits-weight split (row-major)
    k_packB<<<dim3(VPAD/64, 16), 256>>>(outW);
    // recurrent-weight fragment packs
    const float* Wu0h = Wu0 + (long)EE*HH;
    const float* Wr0h = Wr0 + (long)EE*HH;
    const float* Wc0h = Wc0 + (long)EE*HH;
    k_packWF<<<dim3(32, 32), 32>>>(Wu0h, pW0F + (long)0*65536, 32);
    k_packWF<<<dim3(32, 32), 32>>>(Wr0h, pW0F + (long)1*65536, 32);
    k_packWF<<<dim3(32, 32), 32>>>(Wc0h, pW0F + (long)2*65536, 32);
    k_packWF<<<dim3(32, 64), 32>>>(Wu1,  pW1F + (long)0*131072, 64);
    k_packWF<<<dim3(32, 64), 32>>>(Wr1,  pW1F + (long)1*131072, 64);
    k_packWF<<<dim3(32, 64), 32>>>(Wc1,  pW1F + (long)2*131072, 64);
    // layer-0 x-projections for ALL timesteps
    k_gemmL<0><<<dim3(8, 32), 256>>>(pemb, Wu0, bu0, pXU, 4096, 512, 512, 512, 512, 512);
    k_gemmL<0><<<dim3(8, 32), 256>>>(pemb, Wr0, br0, pXR, 4096, 512, 512, 512, 512, 512);
    k_gemmL<0><<<dim3(8, 32), 256>>>(pemb, Wc0, bc0, pXC, 4096, 512, 512, 512, 512, 512);
    // h0 fragment split
    k_splitH0F<<<dim3(8, 32), 32>>>();

    // persistent tensor-core recurrent kernel (register-direct fragments)
    k_reset<<<1, 1>>>();
    k_recurrentF<<<NCTA_R, 128>>>(bu1, br1, bc1);

    // logits (g_A2 row-major filled by phase D)
    k_logits_mma<<<dim3(VPAD/128, 32), 256, 2*BUFB>>>(outb, out);

    // final_state (t=31 odd -> g_H0b holds layer0 final)
    k_copy_final<<<(BB*HH + 255)/256, 256>>>(pH0b, pH1 + (long)(TT-1)*BB*HH,
                                             out + (long)BB*TT*VV);
}

// round 9
// speedup vs baseline: 1.7588x; 1.0273x over previous
#include <cuda_runtime.h>
#include <cuda_bf16.h>
#include <cstdint>
#include <stdint.h>
#include <math.h>

#define BB 128
#define TT 32
#define EE 512
#define HH 512
#define VV 10000
#define CF 2048
#define VPAD 10112            // 632 n-tiles of 16

#define NCTA_R 128

typedef unsigned long long ull;

// ---------------- scratch (device globals; no allocations allowed) ----------
__device__ float g_h0[BB*HH];
__device__ float g_emb[TT*BB*EE];
__device__ float g_XU[TT*BB*HH];
__device__ float g_XR[TT*BB*HH];
__device__ float g_XC[TT*BB*HH];
__device__ float g_H0a[BB*HH];
__device__ float g_H0b[BB*HH];
__device__ float g_H1[TT*BB*HH];
__device__ float g_u[BB*HH];
__device__ unsigned g_bar;
__device__ unsigned g_gen;
// fragment buffers: tile = 32 lanes x 16B, [kt][pl2][lane32] = 64 uint4/tile
__device__ uint4 g_A2F[TT*16384];        // h1 splits per t: [t][mt8][kt32][pl2][ln32]
__device__ uint4 g_B2F[632*2048];        // out_W frags: [nt632][kt32][pl2][ln32]
__device__ uint4 g_H0sF[16384];          // h0 split frags [mt8][kt32][pl2][ln32]
__device__ uint4 g_h0sF[16384];          // initial h0 frags (h1prev at t=0)
__device__ uint4 g_rhsF[16384];          // r*h split frags
// weight frags: [gate][nt32][kt][pl2][lane32]
__device__ uint4 g_W0F[3*65536];
__device__ uint4 g_W1F[3*131072];

__device__ __forceinline__ float sigmoidf_(float v){ return 1.f/(1.f+__expf(-v)); }

// packed f32x2 helpers (FFMA2 prep GEMMs)
__device__ __forceinline__ void fma2(ull &acc, ull a, ull b){
    asm("fma.rn.f32x2 %0, %1, %2, %0;" : "+l"(acc) : "l"(a), "l"(b));
}
__device__ __forceinline__ ull dup2(float x){
    ull r; asm("mov.b64 %0, {%1, %1};" : "=l"(r) : "f"(x)); return r;
}
__device__ __forceinline__ float2 unp2(ull v){
    float2 f; asm("mov.b64 {%0, %1}, %2;" : "=f"(f.x), "=f"(f.y) : "l"(v)); return f;
}

// ---------------- mma helper -------------------------------------------------
__device__ __forceinline__ void mmaU(float* d, const uint4 &a, uint32_t b0, uint32_t b1){
    asm volatile("mma.sync.aligned.m16n8k16.row.col.f32.bf16.bf16.f32 "
        "{%0,%1,%2,%3}, {%4,%5,%6,%7}, {%8,%9}, {%0,%1,%2,%3};"
        : "+f"(d[0]), "+f"(d[1]), "+f"(d[2]), "+f"(d[3])
        : "r"(a.x), "r"(a.y), "r"(a.z), "r"(a.w), "r"(b0), "r"(b1));
}

// split/pack helpers
__device__ __forceinline__ uint32_t bfpair(float a, float b){
    __nv_bfloat162 t = __floats2bfloat162_rn(a, b);
    return *reinterpret_cast<uint32_t*>(&t);
}
__device__ __forceinline__ float bfres(float a){
    return a - __bfloat162float(__float2bfloat16(a));
}
// v[g][0..3] = values at (r,cg),(r,cg+1),(r+8,cg),(r+8,cg+1) for groups g=0,1
__device__ __forceinline__ void store_frag(uint4* dst, const float v[2][4]){
    uint4 HI, LO;
    HI.x = bfpair(v[0][0], v[0][1]); HI.y = bfpair(v[0][2], v[0][3]);
    HI.z = bfpair(v[1][0], v[1][1]); HI.w = bfpair(v[1][2], v[1][3]);
    LO.x = bfpair(bfres(v[0][0]), bfres(v[0][1]));
    LO.y = bfpair(bfres(v[0][2]), bfres(v[0][3]));
    LO.z = bfpair(bfres(v[1][0]), bfres(v[1][1]));
    LO.w = bfpair(bfres(v[1][2]), bfres(v[1][3]));
    __stcg(dst, HI);
    __stcg(dst + 32, LO);
}

// ---------------- embedding gather ------------------------------------------
__global__ void k_gather(const int* __restrict__ tok, const float* __restrict__ emb){
    int row = blockIdx.x;            // t*BB + b
    int t = row >> 7, b = row & 127;
    int v = tok[b*TT + t];
    const float4* src = (const float4*)(emb + (long)v*EE);
    float4* dst = (float4*)(g_emb + (long)row*EE);
    dst[threadIdx.x] = src[threadIdx.x];
}

// ---------------- big fp32 GEMM, 128x64 tile, FFMA2 (prep + h0) -------------
template<int EPI>
__global__ void __launch_bounds__(256)
k_gemmL(const float* __restrict__ A, const float* __restrict__ Bm,
        const float* __restrict__ bias, float* __restrict__ C,
        int M, int N, int K, int lda, int ldb, int ldc)
{
    __shared__ __align__(16) float As[16*132];
    __shared__ __align__(16) float Bs[16*68];
    int tid = threadIdx.x;
    int ty = tid >> 4, tx = tid & 15;
    int m0 = blockIdx.y * 128, n0 = blockIdx.x * 64;
    int ar = tid >> 1, ac = (tid & 1) * 8;
    int br = tid >> 4, bc = (tid & 15) * 4;
    bool bok = (n0 + bc) < N;

    ull acc[4][4] = {};
    float4 a0, a1, b0;

    a0 = *(const float4*)(A + (long)(m0+ar)*lda + ac);
    a1 = *(const float4*)(A + (long)(m0+ar)*lda + ac + 4);
    b0 = bok ? *(const float4*)(Bm + (long)br*ldb + n0 + bc)
             : make_float4(0.f,0.f,0.f,0.f);
    As[(ac+0)*132+ar]=a0.x; As[(ac+1)*132+ar]=a0.y; As[(ac+2)*132+ar]=a0.z; As[(ac+3)*132+ar]=a0.w;
    As[(ac+4)*132+ar]=a1.x; As[(ac+5)*132+ar]=a1.y; As[(ac+6)*132+ar]=a1.z; As[(ac+7)*132+ar]=a1.w;
    *(float4*)&Bs[br*68+bc] = b0;
    __syncthreads();

    int nch = K >> 4;
    for (int ch = 1; ch <= nch; ch++){
        if (ch < nch){
            int k0 = ch * 16;
            a0 = *(const float4*)(A + (long)(m0+ar)*lda + k0 + ac);
            a1 = *(const float4*)(A + (long)(m0+ar)*lda + k0 + ac + 4);
            b0 = bok ? *(const float4*)(Bm + (long)(k0+br)*ldb + n0 + bc)
                     : make_float4(0.f,0.f,0.f,0.f);
        }
#pragma unroll
        for (int kk = 0; kk < 16; kk++){
            ull av[4];
#pragma unroll
            for (int p = 0; p < 4; p++)
                av[p] = *(const ull*)(As + kk*132 + ty*8 + 2*p);
            float4 bv = *(const float4*)(Bs + kk*68 + tx*4);
            ull bb0 = dup2(bv.x), bb1 = dup2(bv.y), bb2 = dup2(bv.z), bb3 = dup2(bv.w);
#pragma unroll
            for (int p = 0; p < 4; p++){
                fma2(acc[p][0], av[p], bb0);
                fma2(acc[p][1], av[p], bb1);
                fma2(acc[p][2], av[p], bb2);
                fma2(acc[p][3], av[p], bb3);
            }
        }
        if (ch < nch){
            __syncthreads();
            As[(ac+0)*132+ar]=a0.x; As[(ac+1)*132+ar]=a0.y; As[(ac+2)*132+ar]=a0.z; As[(ac+3)*132+ar]=a0.w;
            As[(ac+4)*132+ar]=a1.x; As[(ac+5)*132+ar]=a1.y; As[(ac+6)*132+ar]=a1.z; As[(ac+7)*132+ar]=a1.w;
            *(float4*)&Bs[br*68+bc] = b0;
            __syncthreads();
        }
    }

#pragma unroll
    for (int p = 0; p < 4; p++){
#pragma unroll
        for (int j = 0; j < 4; j++){
            float2 v = unp2(acc[p][j]);
            int n = n0 + tx*4 + j;
            if (n < N){
                float bz = bias[n];
                float r0 = v.x + bz, r1 = v.y + bz;
                if (EPI == 1){ r0 = tanhf(r0); r1 = tanhf(r1); }
                int row0 = ty*8 + 2*p;
                C[(long)(m0+row0)*ldc + n] = r0;
                C[(long)(m0+row0+1)*ldc + n] = r1;
            }
        }
    }
}

// ---------------- packers ---------------------------------------------------
// weight W [K,512] -> frag layout [nt][kt][pl][lane] (B-fragment word order)
__global__ void k_packWF(const float* __restrict__ W, uint4* __restrict__ dst, int KT){
    int nt = blockIdx.x, kt = blockIdx.y, l = threadIdx.x;
    int n0 = nt*16 + (l >> 2), k0 = kt*16 + (l & 3)*2;
    float v[2][4];
    v[0][0] = W[(long)(k0  )*HH + n0];   v[0][1] = W[(long)(k0+1)*HH + n0];
    v[0][2] = W[(long)(k0+8)*HH + n0];   v[0][3] = W[(long)(k0+9)*HH + n0];
    v[1][0] = W[(long)(k0  )*HH + n0+8]; v[1][1] = W[(long)(k0+1)*HH + n0+8];
    v[1][2] = W[(long)(k0+8)*HH + n0+8]; v[1][3] = W[(long)(k0+9)*HH + n0+8];
    store_frag(dst + (long)((nt*KT + kt)*2)*32 + l, v);
}

// out_W [512,10000] -> B-fragment layout with zero pad (stride VV, bounds)
__global__ void k_packBF(const float* __restrict__ W){
    int nt = blockIdx.x, kt = blockIdx.y, l = threadIdx.x;
    int n0 = nt*16 + (l >> 2), k0 = kt*16 + (l & 3)*2;
    float v[2][4];
#pragma unroll
    for (int h = 0; h < 2; h++){
        int n = n0 + h*8;
        if (n < VV){
            v[h][0] = W[(long)(k0  )*VV + n]; v[h][1] = W[(long)(k0+1)*VV + n];
            v[h][2] = W[(long)(k0+8)*VV + n]; v[h][3] = W[(long)(k0+9)*VV + n];
        } else {
            v[h][0] = v[h][1] = v[h][2] = v[h][3] = 0.f;
        }
    }
    store_frag(&g_B2F[0] + (nt*32 + kt)*64 + l, v);
}

// split initial h0 -> A-fragment buffers g_H0sF + g_h0sF
__global__ void k_splitH0F(){
    int mt = blockIdx.x, kt = blockIdx.y, l = threadIdx.x;
    int m0 = mt*16 + (l >> 2), k0 = kt*16 + (l & 3)*2;
    float v[2][4];
    v[0][0] = g_h0[(m0  )*HH + k0];   v[0][1] = g_h0[(m0  )*HH + k0+1];
    v[0][2] = g_h0[(m0+8)*HH + k0];   v[0][3] = g_h0[(m0+8)*HH + k0+1];
    v[1][0] = g_h0[(m0  )*HH + k0+8]; v[1][1] = g_h0[(m0  )*HH + k0+9];
    v[1][2] = g_h0[(m0+8)*HH + k0+8]; v[1][3] = g_h0[(m0+8)*HH + k0+9];
    int off = (mt*32 + kt)*64 + l;
    store_frag(&g_H0sF[0] + off, v);
    store_frag(&g_h0sF[0] + off, v);
}

// ---------------- register-direct fragment logits GEMM ----------------------
// grid (158, 32): CTA = 128 rows (one t) x 64 cols (4 nt); 8 warps of 32x32.
__global__ void __launch_bounds__(256)
k_logits_frag(const float* __restrict__ bias, float* __restrict__ out)
{
    int lane = threadIdx.x & 31, w = threadIdx.x >> 5;
    int t = blockIdx.y;
    int ntb = blockIdx.x * 4;
    int mg = w >> 1, ng = w & 1;

    const uint4* A0 = &g_A2F[0] + t*16384 + (mg*2+0)*2048 + lane;
    const uint4* A1 = &g_A2F[0] + t*16384 + (mg*2+1)*2048 + lane;
    const uint4* B0 = &g_B2F[0] + (ntb + ng*2 + 0)*2048 + lane;
    const uint4* B1 = &g_B2F[0] + (ntb + ng*2 + 1)*2048 + lane;

    float acc[2][2][2][4];
#pragma unroll
    for (int i = 0; i < 2; i++)
#pragma unroll
        for (int j = 0; j < 2; j++)
#pragma unroll
            for (int g = 0; g < 2; g++)
#pragma unroll
                for (int q = 0; q < 4; q++) acc[i][j][g][q] = 0.f;

    uint4 a0h = A0[0], a0l = A0[32], a1h = A1[0], a1l = A1[32];
    uint4 b0h = B0[0], b0l = B0[32], b1h = B1[0], b1l = B1[32];
#pragma unroll 4
    for (int kt = 0; kt < 32; kt++){
        uint4 na0h, na0l, na1h, na1l, nb0h, nb0l, nb1h, nb1l;
        if (kt + 1 < 32){
            int o = (kt+1)*64;
            na0h = A0[o]; na0l = A0[o+32]; na1h = A1[o]; na1l = A1[o+32];
            nb0h = B0[o]; nb0l = B0[o+32]; nb1h = B1[o]; nb1l = B1[o+32];
        } else {
            na0h=a0h; na0l=a0l; na1h=a1h; na1l=a1l;
            nb0h=b0h; nb0l=b0l; nb1h=b1h; nb1l=b1l;
        }
        // (0,0)
        mmaU(acc[0][0][0], a0h, b0h.x, b0h.y); mmaU(acc[0][0][1], a0h, b0h.z, b0h.w);
        mmaU(acc[0][0][0], a0l, b0h.x, b0h.y); mmaU(acc[0][0][1], a0l, b0h.z, b0h.w);
        mmaU(acc[0][0][0], a0h, b0l.x, b0l.y); mmaU(acc[0][0][1], a0h, b0l.z, b0l.w);
        // (0,1)
        mmaU(acc[0][1][0], a0h, b1h.x, b1h.y); mmaU(acc[0][1][1], a0h, b1h.z, b1h.w);
        mmaU(acc[0][1][0], a0l, b1h.x, b1h.y); mmaU(acc[0][1][1], a0l, b1h.z, b1h.w);
        mmaU(acc[0][1][0], a0h, b1l.x, b1l.y); mmaU(acc[0][1][1], a0h, b1l.z, b1l.w);
        // (1,0)
        mmaU(acc[1][0][0], a1h, b0h.x, b0h.y); mmaU(acc[1][0][1], a1h, b0h.z, b0h.w);
        mmaU(acc[1][0][0], a1l, b0h.x, b0h.y); mmaU(acc[1][0][1], a1l, b0h.z, b0h.w);
        mmaU(acc[1][0][0], a1h, b0l.x, b0l.y); mmaU(acc[1][0][1], a1h, b0l.z, b0l.w);
        // (1,1)
        mmaU(acc[1][1][0], a1h, b1h.x, b1h.y); mmaU(acc[1][1][1], a1h, b1h.z, b1h.w);
        mmaU(acc[1][1][0], a1l, b1h.x, b1h.y); mmaU(acc[1][1][1], a1l, b1h.z, b1h.w);
        mmaU(acc[1][1][0], a1h, b1l.x, b1l.y); mmaU(acc[1][1][1], a1h, b1l.z, b1l.w);

        a0h=na0h; a0l=na0l; a1h=na1h; a1l=na1l;
        b0h=nb0h; b0l=nb0l; b1h=nb1h; b1l=nb1l;
    }

    int lr = lane >> 2, lc2 = (lane & 3) * 2;
    long sB = TT * (long)VV;
#pragma unroll
    for (int i = 0; i < 2; i++){
        int b = mg*32 + i*16 + lr;
        long base = (long)b*sB + (long)t*VV;
#pragma unroll
        for (int j = 0; j < 2; j++){
#pragma unroll
            for (int g = 0; g < 2; g++){
                int n = (ntb + ng*2 + j)*16 + g*8 + lc2;
                const float* a4 = acc[i][j][g];
                if (n < VV){
                    float bz = bias[n];
                    out[base + n]        = a4[0] + bz;
                    out[base + 8*sB + n] = a4[2] + bz;
                }
                if (n + 1 < VV){
                    float bz = bias[n+1];
                    out[base + n + 1]        = a4[1] + bz;
                    out[base + 8*sB + n + 1] = a4[3] + bz;
                }
            }
        }
    }
}

// ---------------- barrier reset + grid barrier ------------------------------
__global__ void k_reset(){ g_bar = 0u; g_gen = 0u; }

__device__ __forceinline__ void gsyncN(unsigned &my_gen){
    __syncthreads();
    if (threadIdx.x == 0){
        __threadfence();
        my_gen++;
        if (atomicAdd(&g_bar, 1u) == NCTA_R-1u){
            atomicExch(&g_bar, 0u);
            __threadfence();
            atomicExch(&g_gen, my_gen);
        } else {
            while (*(volatile unsigned*)&g_gen < my_gen) { }
            __threadfence();
        }
    }
    __syncthreads();
}

// ---------------- register-direct fragment GEMM (recurrent) -----------------
template<int KT>
__device__ __forceinline__ void frag_mm(const uint4* __restrict__ A0,
                                        const uint4* __restrict__ A1,
                                        const uint4* __restrict__ Wb,
                                        float acc[2][4])
{
#pragma unroll
    for (int g = 0; g < 2; g++)
#pragma unroll
        for (int q = 0; q < 4; q++) acc[g][q] = 0.f;

    uint4 cAh = __ldcg(A0), cAl = __ldcg(A0 + 32);
    uint4 cWh = Wb[0], cWl = Wb[32];
#pragma unroll 4
    for (int kt = 0; kt < KT; kt++){
        uint4 nAh, nAl, nWh, nWl;
        if (kt + 1 < KT){
            const uint4* an = ((kt+1) < 32) ? (A0 + (kt+1)*64) : (A1 + (kt+1-32)*64);
            nAh = __ldcg(an); nAl = __ldcg(an + 32);
            nWh = Wb[(kt+1)*64]; nWl = Wb[(kt+1)*64 + 32];
        } else { nAh = cAh; nAl = cAl; nWh = cWh; nWl = cWl; }
        mmaU(acc[0], cAh, cWh.x, cWh.y); mmaU(acc[1], cAh, cWh.z, cWh.w);
        mmaU(acc[0], cAl, cWh.x, cWh.y); mmaU(acc[1], cAl, cWh.z, cWh.w);
        mmaU(acc[0], cAh, cWl.x, cWl.y); mmaU(acc[1], cAh, cWl.z, cWl.w);
        cAh = nAh; cAl = nAl; cWh = nWh; cWl = nWl;
    }
}

// ---------------- persistent recurrent kernel (fragment mma) ----------------
__global__ void __launch_bounds__(128, 1)
k_recurrentF(const float* __restrict__ bu1, const float* __restrict__ br1,
             const float* __restrict__ bc1)
{
    int tid = threadIdx.x, w = tid >> 5, lane = tid & 31;
    int gw = blockIdx.x * 4 + w;            // 0..511
    int lr = lane >> 2, lc2 = (lane & 3) * 2;
    unsigned my_gen = 0;

    int gate = gw >> 8;
    int ntA  = (gw >> 3) & 31;
    int mtA  = gw & 7;
    bool actBD = (gw & 1) == 0;
    int u2  = gw >> 1;
    int ntB = (u2 >> 3) & 31;
    int mtB = u2 & 7;

    const uint4* WA0 = &g_W0F[0] + (long)gate*65536 + ntA*2048 + lane;
    const uint4* WB0 = &g_W0F[0] + (long)2*65536   + ntB*2048 + lane;
    const uint4* WA1 = &g_W1F[0] + (long)gate*131072 + ntA*4096 + lane;
    const uint4* WB1 = &g_W1F[0] + (long)2*131072   + ntB*4096 + lane;

    for (int t = 0; t < TT; t++){
        const float* h0prev = (t == 0) ? g_h0 : ((t & 1) ? g_H0a : g_H0b);
        float*       h0cur  = (t & 1) ? g_H0b : g_H0a;
        const float* h1prev = (t == 0) ? g_h0 : g_H1 + (t-1)*BB*HH;
        float*       h1cur  = g_H1 + t*BB*HH;
        const float* XU = g_XU + t*BB*HH;
        const float* XR = g_XR + t*BB*HH;
        const float* XC = g_XC + t*BB*HH;
        const uint4* h1sF = (t == 0) ? &g_h0sF[0] : &g_A2F[0] + (t-1)*16384;

        // --- Phase A: u0 / r0 (K=512, A = h0prev frags) ---
        {
            float acc[2][4];
            const uint4* A0 = &g_H0sF[0] + mtA*2048 + lane;
            frag_mm<32>(A0, A0, WA0, acc);
            int r0 = mtA*16 + lr;
            if (gate == 0){
#pragma unroll
                for (int g = 0; g < 2; g++){
                    int cg = ntA*16 + g*8 + lc2;
                    int i0 = r0*HH + cg, i1 = (r0+8)*HH + cg;
                    __stcg(&g_u[i0],   sigmoidf_(acc[g][0] + XU[i0]));
                    __stcg(&g_u[i0+1], sigmoidf_(acc[g][1] + XU[i0+1]));
                    __stcg(&g_u[i1],   sigmoidf_(acc[g][2] + XU[i1]));
                    __stcg(&g_u[i1+1], sigmoidf_(acc[g][3] + XU[i1+1]));
                }
            } else {
                float vv[2][4];
#pragma unroll
                for (int g = 0; g < 2; g++){
                    int cg = ntA*16 + g*8 + lc2;
                    int i0 = r0*HH + cg, i1 = (r0+8)*HH + cg;
                    vv[g][0] = sigmoidf_(acc[g][0] + XR[i0])   * __ldcg(&h0prev[i0]);
                    vv[g][1] = sigmoidf_(acc[g][1] + XR[i0+1]) * __ldcg(&h0prev[i0+1]);
                    vv[g][2] = sigmoidf_(acc[g][2] + XR[i1])   * __ldcg(&h0prev[i1]);
                    vv[g][3] = sigmoidf_(acc[g][3] + XR[i1+1]) * __ldcg(&h0prev[i1+1]);
                }
                store_frag(&g_rhsF[0] + mtA*2048 + ntA*64 + lane, vv);
            }
        }
        gsyncN(my_gen);

        // --- Phase B: c0 + blend -> h0cur (K=512, A = rh frags) ---
        if (actBD){
            float acc[2][4];
            const uint4* A0 = &g_rhsF[0] + mtB*2048 + lane;
            frag_mm<32>(A0, A0, WB0, acc);
            int r0 = mtB*16 + lr;
            float vv[2][4];
#pragma unroll
            for (int g = 0; g < 2; g++){
                int cg = ntB*16 + g*8 + lc2;
                int idx[4] = { r0*HH + cg, r0*HH + cg + 1,
                               (r0+8)*HH + cg, (r0+8)*HH + cg + 1 };
#pragma unroll
                for (int j = 0; j < 4; j++){
                    float c0 = tanhf(acc[g][j] + XC[idx[j]]);
                    float uu = __ldcg(&g_u[idx[j]]);
                    float hp = __ldcg(&h0prev[idx[j]]);
                    float hn = uu*hp + (1.f - uu)*c0;
                    __stcg(&h0cur[idx[j]], hn);
                    vv[g][j] = hn;
                }
            }
            store_frag(&g_H0sF[0] + mtB*2048 + ntB*64 + lane, vv);
        }
        gsyncN(my_gen);

        // --- Phase C: u1 / r1 (K=1024, A = [h0cur | h1prev] frags) ---
        {
            float acc[2][4];
            const uint4* A0 = &g_H0sF[0] + mtA*2048 + lane;
            const uint4* A1 = h1sF + mtA*2048 + lane;
            frag_mm<64>(A0, A1, WA1, acc);
            int r0 = mtA*16 + lr;
            if (gate == 0){
#pragma unroll
                for (int g = 0; g < 2; g++){
                    int cg = ntA*16 + g*8 + lc2;
                    int i0 = r0*HH + cg, i1 = (r0+8)*HH + cg;
                    __stcg(&g_u[i0],   sigmoidf_(acc[g][0] + bu1[cg]));
                    __stcg(&g_u[i0+1], sigmoidf_(acc[g][1] + bu1[cg+1]));
                    __stcg(&g_u[i1],   sigmoidf_(acc[g][2] + bu1[cg]));
                    __stcg(&g_u[i1+1], sigmoidf_(acc[g][3] + bu1[cg+1]));
                }
            } else {
                float vv[2][4];
#pragma unroll
                for (int g = 0; g < 2; g++){
                    int cg = ntA*16 + g*8 + lc2;
                    int i0 = r0*HH + cg, i1 = (r0+8)*HH + cg;
                    vv[g][0] = sigmoidf_(acc[g][0] + br1[cg])   * __ldcg(&h1prev[i0]);
                    vv[g][1] = sigmoidf_(acc[g][1] + br1[cg+1]) * __ldcg(&h1prev[i0+1]);
                    vv[g][2] = sigmoidf_(acc[g][2] + br1[cg])   * __ldcg(&h1prev[i1]);
                    vv[g][3] = sigmoidf_(acc[g][3] + br1[cg+1]) * __ldcg(&h1prev[i1+1]);
                }
                store_frag(&g_rhsF[0] + mtA*2048 + ntA*64 + lane, vv);
            }
        }
        gsyncN(my_gen);

        // --- Phase D: c1 + blend -> h1cur + A-frags (K=1024) ---
        if (actBD){
            float acc[2][4];
            const uint4* A0 = &g_H0sF[0] + mtB*2048 + lane;
            const uint4* A1 = &g_rhsF[0] + mtB*2048 + lane;
            frag_mm<64>(A0, A1, WB1, acc);
            int r0 = mtB*16 + lr;
            float vv[2][4];
#pragma unroll
            for (int g = 0; g < 2; g++){
                int cg = ntB*16 + g*8 + lc2;
#pragma unroll
                for (int j = 0; j < 4; j++){
                    int row = r0 + ((j >> 1) ? 8 : 0);
                    int col = cg + (j & 1);
                    int idx = row*HH + col;
                    float c1 = tanhf(acc[g][j] + bc1[col]);
                    float uu = __ldcg(&g_u[idx]);
                    float hp = __ldcg(&h1prev[idx]);
                    float hn = uu*hp + (1.f - uu)*c1;
                    __stcg(&h1cur[idx], hn);
                    vv[g][j] = hn;
                }
            }
            // h1 split as A-fragments for both next step (phase C) and logits
            store_frag(&g_A2F[0] + t*16384 + mtB*2048 + ntB*64 + lane, vv);
        }
        gsyncN(my_gen);
    }
}

// ---------------- final state copy ------------------------------------------
__global__ void k_copy_final(const float* __restrict__ h0f,
                             const float* __restrict__ h1f,
                             float* __restrict__ out)
{
    int i = blockIdx.x * blockDim.x + threadIdx.x;
    if (i < BB*HH){
        out[i]         = h0f[i];
        out[BB*HH + i] = h1f[i];
    }
}

// ---------------- launch ----------------------------------------------------
extern "C" void kernel_launch(void* const* d_in, const int* in_sizes, int n_in,
                              void* d_out, int out_size)
{
    const float* cnn = (const float*)d_in[0];
    const int*   tok = (const int*)  d_in[1];
    const float* emb = (const float*)d_in[2];
    const float* inW = (const float*)d_in[3];
    const float* inb = (const float*)d_in[4];
    const float* Wu0 = (const float*)d_in[5];
    const float* bu0 = (const float*)d_in[6];
    const float* Wr0 = (const float*)d_in[7];
    const float* br0 = (const float*)d_in[8];
    const float* Wc0 = (const float*)d_in[9];
    const float* bc0 = (const float*)d_in[10];
    const float* Wu1 = (const float*)d_in[11];
    const float* bu1 = (const float*)d_in[12];
    const float* Wr1 = (const float*)d_in[13];
    const float* br1 = (const float*)d_in[14];
    const float* Wc1 = (const float*)d_in[15];
    const float* bc1 = (const float*)d_in[16];
    const float* outW= (const float*)d_in[17];
    const float* outb= (const float*)d_in[18];
    float* out = (float*)d_out;

    float *ph0,*pemb,*pXU,*pXR,*pXC,*pH0b,*pH1;
    uint4 *pW0F, *pW1F;
    cudaGetSymbolAddress((void**)&ph0,  g_h0);
    cudaGetSymbolAddress((void**)&pemb, g_emb);
    cudaGetSymbolAddress((void**)&pXU,  g_XU);
    cudaGetSymbolAddress((void**)&pXR,  g_XR);
    cudaGetSymbolAddress((void**)&pXC,  g_XC);
    cudaGetSymbolAddress((void**)&pH0b, g_H0b);
    cudaGetSymbolAddress((void**)&pH1,  g_H1);
    cudaGetSymbolAddress((void**)&pW0F, g_W0F);
    cudaGetSymbolAddress((void**)&pW1F, g_W1F);

    // h0 = tanh(cnn @ in_W + in_b)
    k_gemmL<1><<<dim3(8, 1), 256>>>(cnn, inW, inb, ph0, 128, 512, 2048, 2048, 512, 512);
    // gather embeddings
    k_gather<<<TT*BB, 128>>>(tok, emb);
    // logits-weight fragment pack
    k_packBF<<<dim3(632, 32), 32>>>(outW);
    // recurrent-weight fragment packs
    const float* Wu0h = Wu0 + (long)EE*HH;
    const float* Wr0h = Wr0 + (long)EE*HH;
    const float* Wc0h = Wc0 + (long)EE*HH;
    k_packWF<<<dim3(32, 32), 32>>>(Wu0h, pW0F + (long)0*65536, 32);
    k_packWF<<<dim3(32, 32), 32>>>(Wr0h, pW0F + (long)1*65536, 32);
    k_packWF<<<dim3(32, 32), 32>>>(Wc0h, pW0F + (long)2*65536, 32);
    k_packWF<<<dim3(32, 64), 32>>>(Wu1,  pW1F + (long)0*131072, 64);
    k_packWF<<<dim3(32, 64), 32>>>(Wr1,  pW1F + (long)1*131072, 64);
    k_packWF<<<dim3(32, 64), 32>>>(Wc1,  pW1F + (long)2*131072, 64);
    // layer-0 x-projections for ALL timesteps
    k_gemmL<0><<<dim3(8, 32), 256>>>(pemb, Wu0, bu0, pXU, 4096, 512, 512, 512, 512, 512);
    k_gemmL<0><<<dim3(8, 32), 256>>>(pemb, Wr0, br0, pXR, 4096, 512, 512, 512, 512, 512);
    k_gemmL<0><<<dim3(8, 32), 256>>>(pemb, Wc0, bc0, pXC, 4096, 512, 512, 512, 512, 512);
    // h0 fragment split
    k_splitH0F<<<dim3(8, 32), 32>>>();

    // persistent tensor-core recurrent kernel
    k_reset<<<1, 1>>>();
    k_recurrentF<<<NCTA_R, 128>>>(bu1, br1, bc1);

    // register-direct fragment logits
    k_logits_frag<<<dim3(158, 32), 256>>>(outb, out);

    // final_state (t=31 odd -> g_H0b holds layer0 final)
    k_copy_final<<<(BB*HH + 255)/256, 256>>>(pH0b, pH1 + (long)(TT-1)*BB*HH,
                                             out + (long)BB*TT*VV);
}